// round 6
// baseline (speedup 1.0000x reference)
#include <cuda_runtime.h>

#define BATCH        16384
#define NUM_FIELDS   20
#define NUM_FEATURES 100000
#define LATENT_DIM   64

// Two samples per warp (one per half-warp). Per iteration each half-warp
// processes TWO fields: octet 0 (lanes 0-7) field f, octet 1 (lanes 8-15)
// field f+1. Each lane loads 8 dims with a single 256-bit LDG (v8.b32,
// evict_last) -> 10 gather instructions per lane instead of 20.
__device__ __forceinline__ void ldg256(const float* __restrict__ p, float v[8])
{
    unsigned r0, r1, r2, r3, r4, r5, r6, r7;
    asm volatile(
        "ld.global.nc.L2::evict_last.v8.b32 {%0,%1,%2,%3,%4,%5,%6,%7}, [%8];"
        : "=r"(r0), "=r"(r1), "=r"(r2), "=r"(r3),
          "=r"(r4), "=r"(r5), "=r"(r6), "=r"(r7)
        : "l"(p));
    v[0] = __uint_as_float(r0); v[1] = __uint_as_float(r1);
    v[2] = __uint_as_float(r2); v[3] = __uint_as_float(r3);
    v[4] = __uint_as_float(r4); v[5] = __uint_as_float(r5);
    v[6] = __uint_as_float(r6); v[7] = __uint_as_float(r7);
}

__global__ __launch_bounds__(256)
void ffm_kernel(const int* __restrict__ x,
                const float* __restrict__ emb,
                float* __restrict__ out)
{
    const int gwarp = (blockIdx.x * blockDim.x + threadIdx.x) >> 5;
    const int lane  = threadIdx.x & 31;
    const int half  = lane >> 4;          // sample within the warp
    const int lh    = lane & 15;          // lane within half-warp
    const int sub   = lh >> 3;            // octet: which of the 2 fields/iter
    const int lo    = lh & 7;             // lane within octet (owns dims 8*lo..)
    const int s     = gwarp * 2 + half;   // batch sample id
    if (s >= BATCH) return;

    // 20 indices per half-warp: lanes 0..15 hold fields 0..15,
    // lanes 0..3 additionally hold fields 16..19.
    const int* xrow = x + s * NUM_FIELDS;
    int xi0 = __ldg(xrow + lh);                                    // fields 0..15
    int xi1 = (lh < NUM_FIELDS - 16) ? __ldg(xrow + 16 + lh) : 0;  // fields 16..19

    float sv[8] = {0.f, 0.f, 0.f, 0.f, 0.f, 0.f, 0.f, 0.f};
    float sq = 0.f;

    #pragma unroll
    for (int f = 0; f < NUM_FIELDS; f += 2) {
        const int g = f + sub;            // this lane's field for the iteration
        int idx;
        if (f < 16) idx = __shfl_sync(0xffffffffu, xi0, g, 16);
        else        idx = __shfl_sync(0xffffffffu, xi1, g - 16, 16);

        const float* p = emb + ((size_t)g * NUM_FEATURES + (size_t)idx) * LATENT_DIM
                             + lo * 8;
        float v[8];
        ldg256(p, v);

        #pragma unroll
        for (int i = 0; i < 8; ++i) {
            sv[i] += v[i];
            sq = fmaf(v[i], v[i], sq);
        }
    }

    // Fold the two octets' field-partials per dim, then square.
    float ssq = 0.f;
    #pragma unroll
    for (int i = 0; i < 8; ++i) {
        const float t = sv[i] + __shfl_xor_sync(0xffffffffu, sv[i], 8, 16);
        ssq = fmaf(t, t, ssq);
    }
    float sq2  = sq + __shfl_xor_sync(0xffffffffu, sq, 8, 16);
    int   lin  = xi0 + xi1;
    int   lin2 = lin + __shfl_xor_sync(0xffffffffu, lin, 8, 16);

    float val = ssq - sq2;
    #pragma unroll
    for (int o = 4; o > 0; o >>= 1) {
        val  += __shfl_xor_sync(0xffffffffu, val,  o, 16);
        lin2 += __shfl_xor_sync(0xffffffffu, lin2, o, 16);
    }

    if (lh == 0)
        out[s] = (float)lin2 + 0.5f * val;
}

extern "C" void kernel_launch(void* const* d_in, const int* in_sizes, int n_in,
                              void* d_out, int out_size)
{
    const int*   x   = (const int*)d_in[0];     // (16384, 20) int32
    // d_in[1] = field_indices (arange(20)) — identity, unused
    const float* emb = (const float*)d_in[2];   // (20, 100000, 64) fp32
    float*       out = (float*)d_out;           // (16384,) fp32

    const int threads = 256;                    // 8 warps = 16 samples / block
    const int warps   = (BATCH + 1) / 2;        // 8192 warps
    const int blocks  = (warps * 32 + threads - 1) / threads;  // 1024
    ffm_kernel<<<blocks, threads>>>(x, emb, out);
}

// round 7
// speedup vs baseline: 1.2179x; 1.2179x over previous
#include <cuda_runtime.h>

#define BATCH        16384
#define NUM_FIELDS   20
#define NUM_FEATURES 100000
#define LATENT_DIM   64

// R2 layout (best so far): two samples per warp, one per half-warp; each lane
// owns 4 of 64 dims -> LDG.128 per embedding row; 8192 warps (~51/SM).
// New: the 20 gathers are issued as TWO groups of 10 with a scheduling barrier
// between them, halving the front-batched LDG burst (MLP_p1 20 -> 10) to cut
// cross-CTA L1tex wavefront-queue contention (end-of-kernel straggler spread).
__global__ __launch_bounds__(256)
void ffm_kernel(const int* __restrict__ x,
                const float* __restrict__ emb,
                float* __restrict__ out)
{
    const int gwarp = (blockIdx.x * blockDim.x + threadIdx.x) >> 5;
    const int lane  = threadIdx.x & 31;
    const int half  = lane >> 4;          // sample within the warp
    const int lh    = lane & 15;          // lane within half-warp
    const int s     = gwarp * 2 + half;   // batch sample id
    if (s >= BATCH) return;

    // 20 indices per half-warp: lanes 0..15 hold fields 0..15,
    // lanes 0..3 additionally hold fields 16..19.
    const int* xrow = x + s * NUM_FIELDS;
    int xi0 = __ldg(xrow + lh);                                    // fields 0..15
    int xi1 = (lh < NUM_FIELDS - 16) ? __ldg(xrow + 16 + lh) : 0;  // fields 16..19

    float4 sv = make_float4(0.f, 0.f, 0.f, 0.f);   // partial of sum_f V[f]
    float  sq = 0.f;                               // partial of sum V^2

    // ---- Group 1: fields 0..9 ----
    float4 g1[10];
    #pragma unroll
    for (int f = 0; f < 10; ++f) {
        const int idx = __shfl_sync(0xffffffffu, xi0, f, 16);
        const float4* row = reinterpret_cast<const float4*>(
            emb + ((size_t)f * NUM_FEATURES + (size_t)idx) * LATENT_DIM);
        g1[f] = __ldg(row + lh);
    }
    #pragma unroll
    for (int f = 0; f < 10; ++f) {
        const float4 v = g1[f];
        sv.x += v.x;  sv.y += v.y;  sv.z += v.z;  sv.w += v.w;
        sq = fmaf(v.x, v.x, sq);  sq = fmaf(v.y, v.y, sq);
        sq = fmaf(v.z, v.z, sq);  sq = fmaf(v.w, v.w, sq);
    }

    // Prevent ptxas from hoisting group-2 LDGs above group-1 consumption.
    asm volatile("" ::: "memory");

    // ---- Group 2: fields 10..19 ----
    float4 g2[10];
    #pragma unroll
    for (int f = 10; f < NUM_FIELDS; ++f) {
        int idx;
        if (f < 16) idx = __shfl_sync(0xffffffffu, xi0, f, 16);
        else        idx = __shfl_sync(0xffffffffu, xi1, f - 16, 16);
        const float4* row = reinterpret_cast<const float4*>(
            emb + ((size_t)f * NUM_FEATURES + (size_t)idx) * LATENT_DIM);
        g2[f - 10] = __ldg(row + lh);
    }
    #pragma unroll
    for (int f = 0; f < 10; ++f) {
        const float4 v = g2[f];
        sv.x += v.x;  sv.y += v.y;  sv.z += v.z;  sv.w += v.w;
        sq = fmaf(v.x, v.x, sq);  sq = fmaf(v.y, v.y, sq);
        sq = fmaf(v.z, v.z, sq);  sq = fmaf(v.w, v.w, sq);
    }

    float part = fmaf(sv.x, sv.x, fmaf(sv.y, sv.y,
                 fmaf(sv.z, sv.z, sv.w * sv.w))) - sq;
    int   lin  = xi0 + xi1;

    // Reduce within the 16-lane half-warp.
    #pragma unroll
    for (int o = 8; o > 0; o >>= 1) {
        part += __shfl_xor_sync(0xffffffffu, part, o);
        lin  += __shfl_xor_sync(0xffffffffu, lin,  o);
    }

    if (lh == 0)
        out[s] = (float)lin + 0.5f * part;
}

extern "C" void kernel_launch(void* const* d_in, const int* in_sizes, int n_in,
                              void* d_out, int out_size)
{
    const int*   x   = (const int*)d_in[0];     // (16384, 20) int32
    // d_in[1] = field_indices (arange(20)) — identity, unused
    const float* emb = (const float*)d_in[2];   // (20, 100000, 64) fp32
    float*       out = (float*)d_out;           // (16384,) fp32

    const int threads = 256;                    // 8 warps = 16 samples / block
    const int warps   = (BATCH + 1) / 2;        // 8192 warps
    const int blocks  = (warps * 32 + threads - 1) / threads;  // 1024
    ffm_kernel<<<blocks, threads>>>(x, emb, out);
}